// round 14
// baseline (speedup 1.0000x reference)
#include <cuda_runtime.h>
#include <cuda_bf16.h>
#include <math.h>
#include <cstdint>

// Problem constants
#define BB   32768
#define FF   1024
#define HH   512
#define EE   10
#define CC   10
#define KK   4
#define KC   64        // K chunk per iteration
#define NKC  (FF/KC)   // 16
#define NIT  (KK*NKC)  // 64 iterations

// A/B smem row stride: 72 bf16 = 144 bytes (16B-aligned, conflict-free ldmatrix)
#define RST  144

// ---------------- device scratch (allocation-free) ----------------
__device__ float g_bc[KK * 32];                 // folded biases
// B tiles bf16 hi/lo, padded row-major image: [tile=(k*16+kc)][hi 32x72 | lo 32x72] = 9216 B
// pad columns 64..71 are never written -> stay zero from module load
__device__ __align__(16) __nv_bfloat16 g_Wb[KK * NKC * 2 * 32 * 72];
// qkv staging TRANSPOSED: [c][b], c = k*32+col (16 MB)
__device__ __align__(16) float g_qkv[(size_t)128 * BB];
// grid barrier state (zero-initialized at module load)
__device__ int g_arrive;
__device__ int g_release;

// ---------------- PTX helpers ----------------
__device__ __forceinline__ uint32_t smem_u32(const void* p) {
    uint32_t a;
    asm("{ .reg .u64 t; cvta.to.shared.u64 t, %1; cvt.u32.u64 %0, t; }" : "=r"(a) : "l"(p));
    return a;
}
__device__ __forceinline__ void ldsm4(uint32_t* r, uint32_t addr) {
    asm volatile("ldmatrix.sync.aligned.m8n8.x4.shared.b16 {%0,%1,%2,%3}, [%4];"
        : "=r"(r[0]), "=r"(r[1]), "=r"(r[2]), "=r"(r[3]) : "r"(addr));
}
__device__ __forceinline__ void mma_bf16(float* d, const uint32_t* a, const uint32_t* b) {
    asm volatile("mma.sync.aligned.m16n8k16.row.col.f32.bf16.bf16.f32 "
        "{%0,%1,%2,%3}, {%4,%5,%6,%7}, {%8,%9}, {%0,%1,%2,%3};"
        : "+f"(d[0]), "+f"(d[1]), "+f"(d[2]), "+f"(d[3])
        : "r"(a[0]), "r"(a[1]), "r"(a[2]), "r"(a[3]), "r"(b[0]), "r"(b[1]));
}
__device__ __forceinline__ void cp_async16(uint32_t sdst, const void* gsrc) {
    asm volatile("cp.async.ca.shared.global [%0], [%1], 16;"
        :: "r"(sdst), "l"(gsrc) : "memory");
}
#define CP_COMMIT() asm volatile("cp.async.commit_group;" ::: "memory")
#define CP_WAIT0()  asm volatile("cp.async.wait_group 0;" ::: "memory")
#define CVT_BF16X2(res, a, b) \
    asm("cvt.rn.satfinite.bf16x2.f32 %0, %1, %2;" : "=r"(res) : "f"(b), "f"(a))

// ---------------------------------------------------------------------------
// ONE kernel: in-kernel weight fold + grid barrier + pipelined HMMA GEMM
// + attention epilogue. 256 blocks x 256 threads, all co-resident (2/SM).
// SMEM: [0..512) bias; buffers at 1024 + p*46080:
//   Ahi [0..18432)  Alo [18432..36864)  Bhi [36864..41472)  Blo [41472..46080)
// Phase 0 stages S[8][512] (16 KB) at BUF_BASE; attn staging reuses buffers.
// ---------------------------------------------------------------------------
#define S_BC     0
#define BUF_BASE 1024
#define BUF_SZ   46080
#define A_LO_O   18432
#define B_HI_O   36864
#define SMEM_BYTES (BUF_BASE + 2 * BUF_SZ)   // 93184

__global__ __launch_bounds__(256, 2)
void fused_all(const float* __restrict__ w0, const float* __restrict__ w1,
               const float* __restrict__ w2, const float* __restrict__ w3,
               const float* __restrict__ Wlin, const float* __restrict__ blin,
               const float* __restrict__ Wq, const float* __restrict__ bq,
               const float* __restrict__ Wk, const float* __restrict__ bk,
               const float* __restrict__ Wv, const float* __restrict__ bv,
               const float* __restrict__ Wfin, const float* __restrict__ bfin,
               float* __restrict__ out_outputs, float* __restrict__ out_attn) {
    extern __shared__ char smem[];
    const uint32_t sb = smem_u32(smem);
    const int tid  = threadIdx.x;
    const int wid  = tid >> 5;
    const int lane = tid & 31;
    const int b0   = blockIdx.x * 128;

    // read release epoch BEFORE arriving (stable: release can't fire until all arrive)
    const int epoch0 = *(volatile int*)&g_release;

    // ================= Phase 0: fold my slice of B (and maybe one bias) ======
    {
        const int tile = blockIdx.x >> 2;       // 0..63 = k*16+kc
        const int k0   = tile >> 4;
        const int kc0  = tile & 15;
        const int c0   = (blockIdx.x & 3) * 8;  // 8 c-rows per block

        // stage S[8][512] (rows c0..c0+7 of the small projection matrix)
        float* sS = (float*)(smem + BUF_BASE);
        for (int idx = tid; idx < 8 * 512; idx += 256) {
            int lc = idx >> 9;
            int j  = idx & 511;
            int c  = c0 + lc;
            float v = 0.f;
            if (c < 10)                v = Wq[(k0 * 10 + c) * 512 + j];
            else if (c < 20)           v = Wk[(k0 * 10 + (c - 10)) * 512 + j];
            else if (c < 30 && k0 == 0) v = Wv[(c - 20) * 512 + j];
            sS[idx] = v;
        }
        __syncthreads();

        // each thread: 2 outputs (lc2*2, lc2*2+1) x 1 f
        const int f   = tid & 63;
        const int lc2 = tid >> 6;               // 0..3
        const int lcA = lc2 * 2, lcB = lc2 * 2 + 1;
        float acc0 = 0.f, acc1 = 0.f;
        const float* wl = Wlin + (size_t)k0 * HH * FF + kc0 * KC + f;
#pragma unroll 4
        for (int jb = 0; jb < 512; jb += 8) {
            float wv[8];
#pragma unroll
            for (int t = 0; t < 8; ++t) wv[t] = wl[(size_t)(jb + t) * FF];
#pragma unroll
            for (int t = 0; t < 8; ++t) {
                acc0 += wv[t] * sS[lcA * 512 + jb + t];
                acc1 += wv[t] * sS[lcB * 512 + jb + t];
            }
        }
        // bf16 hi/lo split, write padded image
        {
            size_t base = (size_t)tile * (2 * 32 * 72);
            __nv_bfloat16 h0 = __float2bfloat16(acc0);
            __nv_bfloat16 l0 = __float2bfloat16(acc0 - __bfloat162float(h0));
            __nv_bfloat16 h1 = __float2bfloat16(acc1);
            __nv_bfloat16 l1 = __float2bfloat16(acc1 - __bfloat162float(h1));
            g_Wb[base + (c0 + lcA) * 72 + f]           = h0;
            g_Wb[base + 32 * 72 + (c0 + lcA) * 72 + f] = l0;
            g_Wb[base + (c0 + lcB) * 72 + f]           = h1;
            g_Wb[base + 32 * 72 + (c0 + lcB) * 72 + f] = l1;
        }

        // blocks 0..127: warp 0 folds one bias pair
        if (blockIdx.x < 128 && wid == 0) {
            int gw = blockIdx.x;
            int k = gw >> 5, c = gw & 31;
            const float* W = nullptr;
            float base = 0.f;
            if (c < 10)                { W = Wq + (k * 10 + c) * 512;        base = bq[k * 10 + c]; }
            else if (c < 20)           { W = Wk + (k * 10 + (c - 10)) * 512; base = bk[k * 10 + (c - 10)]; }
            else if (c < 30 && k == 0) { W = Wv + (c - 20) * 512;            base = bv[c - 20]; }
            float s = 0.f;
            if (W) {
                const float* bl = blin + k * 512;
#pragma unroll
                for (int t = 0; t < 16; ++t) s += bl[lane + 32 * t] * W[lane + 32 * t];
            }
#pragma unroll
            for (int o = 16; o; o >>= 1) s += __shfl_xor_sync(0xffffffffu, s, o);
            if (lane == 0) g_bc[gw] = W ? (base + s) : 0.f;
        }
    }

    // ================= grid barrier (all 256 blocks resident) ================
    __threadfence();
    __syncthreads();
    if (tid == 0) {
        int t = atomicAdd(&g_arrive, 1);
        if (t == 255) {
            g_arrive = 0;                 // safe: everyone already arrived
            __threadfence();
            *(volatile int*)&g_release = epoch0 + 1;
        } else {
            while (*(volatile int*)&g_release == epoch0) { }
        }
    }
    __syncthreads();
    __threadfence();

    // ================= Phase 1: pipelined HMMA GEMM ==========================
    const uint32_t aRowOff = (uint32_t)((wid * 32 + (lane & 7) + ((lane >> 3) & 1) * 8) * RST
                                        + (lane >> 4) * 16);
    const uint32_t bRow0   = (uint32_t)((((lane >> 4) & 1) * 8 + (lane & 7)) * RST
                                        + ((lane >> 3) & 1) * 16);

    auto cpasync_B = [&](int j, uint32_t bufbase) {
        const char* src = (const char*)g_Wb + (size_t)j * 9216;
        uint32_t dst = bufbase + B_HI_O;
        cp_async16(dst + (uint32_t)tid * 16,         src + (size_t)tid * 16);
        cp_async16(dst + (uint32_t)(tid + 256) * 16, src + (size_t)(tid + 256) * 16);
        if (tid < 64)
            cp_async16(dst + (uint32_t)(tid + 512) * 16, src + (size_t)(tid + 512) * 16);
        CP_COMMIT();
    };
    auto load_A = [&](int j, float4* va) {
        const int k2 = j >> 4, kc2 = j & 15;
        const float* wk = (k2 == 0) ? w0 : (k2 == 1) ? w1 : (k2 == 2) ? w2 : w3;
#pragma unroll
        for (int u = 0; u < 8; ++u) {
            int idx = tid + u * 256;            // 0..2047
            int row = idx >> 4, f4 = idx & 15;
            va[u] = *(const float4*)(wk + (size_t)(b0 + row) * FF + kc2 * KC + f4 * 4);
        }
    };
    auto convert_sts = [&](char* bb, const float4* va) {
#pragma unroll
        for (int u = 0; u < 8; ++u) {
            int idx = tid + u * 256;
            int row = idx >> 4, f4 = idx & 15;
            int off = row * RST + f4 * 8;
            float4 v = va[u];
            uint32_t hp0, hp1, lp0, lp1;
            CVT_BF16X2(hp0, v.x, v.y);
            CVT_BF16X2(hp1, v.z, v.w);
            float h0 = __uint_as_float(hp0 << 16);
            float h1 = __uint_as_float(hp0 & 0xffff0000u);
            float h2 = __uint_as_float(hp1 << 16);
            float h3 = __uint_as_float(hp1 & 0xffff0000u);
            CVT_BF16X2(lp0, v.x - h0, v.y - h1);
            CVT_BF16X2(lp1, v.z - h2, v.w - h3);
            *(uint2*)(bb + off)          = make_uint2(hp0, hp1);
            *(uint2*)(bb + A_LO_O + off) = make_uint2(lp0, lp1);
        }
    };

    float acc[2][4][4];
#pragma unroll
    for (int mt = 0; mt < 2; ++mt)
#pragma unroll
        for (int nt = 0; nt < 4; ++nt)
#pragma unroll
            for (int i = 0; i < 4; ++i) acc[mt][nt][i] = 0.f;

    float4 va[8];   // pipeline staging: holds A data for iteration i+1

    cpasync_B(0, sb + BUF_BASE);
    load_A(0, va);
    convert_sts(smem + BUF_BASE, va);
    load_A(1, va);
    if (tid < 128) ((float*)(smem + S_BC))[tid] = g_bc[tid];
    CP_WAIT0();
    __syncthreads();

    for (int i = 0; i < NIT; ++i) {
        const uint32_t bufo = sb + BUF_BASE + (uint32_t)(i & 1) * BUF_SZ;
        const bool hn = (i < NIT - 1);

        if (hn) cpasync_B(i + 1, sb + BUF_BASE + (uint32_t)((i + 1) & 1) * BUF_SZ);

        if (wid < 4) {
            const bool do3 = (i >> 4) == 0;     // k==0 has v columns (nt3)
#pragma unroll
            for (int s = 0; s < 4; ++s) {
                const uint32_t so = bufo + (uint32_t)(s * 32);
                uint32_t ah0[4], ah1[4], al0[4], al1[4], bh[8], bl[8];
                ldsm4(ah0, so + aRowOff);
                ldsm4(ah1, so + aRowOff + 16 * RST);
                ldsm4(al0, so + aRowOff + A_LO_O);
                ldsm4(al1, so + aRowOff + A_LO_O + 16 * RST);
                ldsm4(bh,     so + B_HI_O + bRow0);
                ldsm4(bh + 4, so + B_HI_O + bRow0 + 16 * RST);
                ldsm4(bl,     so + B_HI_O + 4608 + bRow0);
                ldsm4(bl + 4, so + B_HI_O + 4608 + bRow0 + 16 * RST);
                mma_bf16(acc[0][0], ah0, bh + 0);
                mma_bf16(acc[0][0], ah0, bl + 0);
                mma_bf16(acc[0][0], al0, bh + 0);
                mma_bf16(acc[0][1], ah0, bh + 2);
                mma_bf16(acc[0][1], ah0, bl + 2);
                mma_bf16(acc[0][1], al0, bh + 2);
                mma_bf16(acc[0][2], ah0, bh + 4);
                mma_bf16(acc[0][2], ah0, bl + 4);
                mma_bf16(acc[0][2], al0, bh + 4);
                if (do3) {
                    mma_bf16(acc[0][3], ah0, bh + 6);
                    mma_bf16(acc[0][3], ah0, bl + 6);
                    mma_bf16(acc[0][3], al0, bh + 6);
                }
                mma_bf16(acc[1][0], ah1, bh + 0);
                mma_bf16(acc[1][0], ah1, bl + 0);
                mma_bf16(acc[1][0], al1, bh + 0);
                mma_bf16(acc[1][1], ah1, bh + 2);
                mma_bf16(acc[1][1], ah1, bl + 2);
                mma_bf16(acc[1][1], al1, bh + 2);
                mma_bf16(acc[1][2], ah1, bh + 4);
                mma_bf16(acc[1][2], ah1, bl + 4);
                mma_bf16(acc[1][2], al1, bh + 4);
                if (do3) {
                    mma_bf16(acc[1][3], ah1, bh + 6);
                    mma_bf16(acc[1][3], ah1, bl + 6);
                    mma_bf16(acc[1][3], al1, bh + 6);
                }
            }
            if ((i & 15) == 15) {
                const int k  = i >> 4;
                const int rr = wid * 32 + (lane >> 2);
                const int cb = (lane & 3) * 2;
#pragma unroll
                for (int mt = 0; mt < 2; ++mt) {
#pragma unroll
                    for (int nt = 0; nt < 4; ++nt) {
                        if (k > 0 && nt == 3) continue;
                        const int c = k * 32 + nt * 8 + cb;
                        const int r = b0 + rr + mt * 16;
                        g_qkv[(size_t)c * BB + r]           = acc[mt][nt][0];
                        g_qkv[(size_t)(c + 1) * BB + r]     = acc[mt][nt][1];
                        g_qkv[(size_t)c * BB + r + 8]       = acc[mt][nt][2];
                        g_qkv[(size_t)(c + 1) * BB + r + 8] = acc[mt][nt][3];
#pragma unroll
                        for (int q = 0; q < 4; ++q) acc[mt][nt][q] = 0.f;
                    }
                }
            }
        }

        if (hn) convert_sts(smem + BUF_BASE + ((i + 1) & 1) * BUF_SZ, va);
        if (i + 2 < NIT) load_A(i + 2, va);

        CP_WAIT0();
        __syncthreads();
    }

    // ================= Phase 2: per-row attention ============================
    float* sAttn = (float*)(smem + BUF_BASE);   // 128 x 100 floats = 51.2 KB
    if (tid < 128) {
        const int b = b0 + tid;
        const float* sBC = (const float*)(smem + S_BC);

        float q[KK][EE], ke[KK][EE], v0[EE];
#pragma unroll
        for (int k = 0; k < KK; ++k)
#pragma unroll
            for (int e = 0; e < EE; ++e) {
                q[k][e]  = g_qkv[(size_t)(k * 32 + e) * BB + b]      + sBC[k * 32 + e];
                ke[k][e] = g_qkv[(size_t)(k * 32 + 10 + e) * BB + b] + sBC[k * 32 + 10 + e];
            }
#pragma unroll
        for (int e = 0; e < EE; ++e)
            v0[e] = g_qkv[(size_t)(20 + e) * BB + b] + sBC[20 + e];

        float w0o[EE];
#pragma unroll
        for (int e = 0; e < EE; ++e) w0o[e] = 0.f;
        const float inv_sqrtE = 0.31622776601683794f;   // 1/sqrt(10)
        float* arow = sAttn + tid * 100;

#pragma unroll
        for (int l = 0; l < EE; ++l) {
            float col[EE];
#pragma unroll
            for (int e = 0; e < EE; ++e)
                col[e] = (q[0][e] * ke[0][l] + q[1][e] * ke[1][l] +
                          q[2][e] * ke[2][l] + q[3][e] * ke[3][l]) * inv_sqrtE;
            float mx = col[0];
#pragma unroll
            for (int e = 1; e < EE; ++e) mx = fmaxf(mx, col[e]);
            float p[EE], s = 0.f;
#pragma unroll
            for (int e = 0; e < EE; ++e) { p[e] = __expf(col[e] - mx); s += p[e]; }
            const float is = 1.f / s;
#pragma unroll
            for (int e = 0; e < EE; ++e) {
                p[e] *= is;
                arow[e * EE + l] = p[e];
                w0o[e] += p[e] * v0[l];
            }
        }

        float oacc[CC];
#pragma unroll
        for (int c = 0; c < CC; ++c) oacc[c] = 0.f;
#pragma unroll
        for (int k = 0; k < KK; ++k) {
            float lg[CC];
#pragma unroll
            for (int c = 0; c < CC; ++c) {
                float s2 = bfin[k * CC + c];
#pragma unroll
                for (int e = 0; e < EE; ++e)
                    s2 += w0o[e] * Wfin[k * CC * EE + c * EE + e];
                lg[c] = s2;
            }
            float mx = lg[0];
#pragma unroll
            for (int c = 1; c < CC; ++c) mx = fmaxf(mx, lg[c]);
            float p[CC], s = 0.f;
#pragma unroll
            for (int c = 0; c < CC; ++c) { p[c] = __expf(lg[c] - mx); s += p[c]; }
            const float is = 1.f / s;
#pragma unroll
            for (int c = 0; c < CC; ++c) oacc[c] += p[c] * is;
        }
        float* outr = out_outputs + (size_t)b * CC;
#pragma unroll
        for (int c = 0; c < CC; ++c) outr[c] = oacc[c] * 0.25f;
    }
    __syncthreads();

    // dense coalesced attn writeback: 128 rows x 100 floats = 3200 float4
    {
        const float4* src = (const float4*)sAttn;
        float4* dst = (float4*)(out_attn + (size_t)b0 * 100);
        for (int t = tid; t < 3200; t += 256) dst[t] = src[t];
    }
}

// ---------------------------------------------------------------------------
extern "C" void kernel_launch(void* const* d_in, const int* in_sizes, int n_in,
                              void* d_out, int out_size) {
    const float* w0   = (const float*)d_in[0];
    const float* w1   = (const float*)d_in[1];
    const float* w2   = (const float*)d_in[2];
    const float* w3   = (const float*)d_in[3];
    const float* Wlin = (const float*)d_in[4];
    const float* blin = (const float*)d_in[5];
    const float* Wq   = (const float*)d_in[6];
    const float* bq   = (const float*)d_in[7];
    const float* Wk   = (const float*)d_in[8];
    const float* bk   = (const float*)d_in[9];
    const float* Wv   = (const float*)d_in[10];
    const float* bv   = (const float*)d_in[11];
    const float* Wfin = (const float*)d_in[12];
    const float* bfin = (const float*)d_in[13];

    float* out      = (float*)d_out;
    float* out_attn = out + (size_t)BB * CC;

    cudaFuncSetAttribute(fused_all, cudaFuncAttributeMaxDynamicSharedMemorySize, SMEM_BYTES);

    fused_all<<<BB / 128, 256, SMEM_BYTES>>>(w0, w1, w2, w3, Wlin, blin,
                                             Wq, bq, Wk, bk, Wv, bv,
                                             Wfin, bfin, out, out_attn);
}